// round 1
// baseline (speedup 1.0000x reference)
#include <cuda_runtime.h>
#include <cstdint>

// Sparse block attention: B=1, H=16, S=8192, D=64, BS=64, NB=128
// Pattern per q-block i: {0} U [max(0,i-7), i]; causal inside diagonal block.
#define HEADS  16
#define SEQ    8192
#define DIM    64
#define BSZ    64
#define NBLK   128
#define LOCALW 8
#define LDK    68   // K tile row stride (floats): 17 quads (odd) -> conflict-free LDS.128 along d
#define LDX    64   // Q/V/P tile row stride (floats)

// dynamic smem: Qs(64*64) + Ks(64*68) + Vs(64*64) + Ps(64*64) floats = 66560 B

__device__ __forceinline__ float ex2f_fast(float x) {
    float y; asm("ex2.approx.ftz.f32 %0, %1;" : "=f"(y) : "f"(x)); return y;
}

__global__ __launch_bounds__(256, 2)
void sparse_attn_fp32(const float* __restrict__ q,
                      const float* __restrict__ k,
                      const float* __restrict__ v,
                      float* __restrict__ out)
{
    extern __shared__ float sm[];
    float* Qs = sm;                    // [64][LDX]
    float* Ks = Qs + BSZ * LDX;        // [64][LDK]
    float* Vs = Ks + BSZ * LDK;        // [64][LDX]
    float* Ps = Vs + BSZ * LDX;        // [64][LDX]

    const int ib  = blockIdx.x;        // q block
    const int h   = blockIdx.y;        // head
    const int tid = threadIdx.x;
    const int ty  = tid >> 4;          // 0..15
    const int tx  = tid & 15;          // 0..15

    // fold sm_scale and log2(e) into Q so scores are already in log2 domain
    const float qscale = 0.125f * 1.4426950408889634f;

    // ---- load + prescale Q tile (fully coalesced float4) ----
    const float* qg = q + ((size_t)h * SEQ + (size_t)ib * BSZ) * DIM;
    #pragma unroll
    for (int t = 0; t < 4; ++t) {
        int qd  = tid + t * 256;           // quad id 0..1023
        int row = qd >> 4;
        int c4  = (qd & 15) << 2;
        float4 val = *(const float4*)(qg + row * DIM + c4);
        val.x *= qscale; val.y *= qscale; val.z *= qscale; val.w *= qscale;
        *(float4*)(Qs + row * LDX + c4) = val;
    }

    float acc[4][4];
    float m_run[4], l_run[4];
    #pragma unroll
    for (int r = 0; r < 4; ++r) {
        m_run[r] = -1e30f; l_run[r] = 0.f;
        #pragma unroll
        for (int c = 0; c < 4; ++c) acc[r][c] = 0.f;
    }

    const int nnz = (ib < LOCALW) ? (ib + 1) : (LOCALW + 1);

    for (int t = 0; t < nnz; ++t) {
        const int jb = (ib < LOCALW) ? t : ((t == 0) ? 0 : (ib - LOCALW + t));

        // ---- load K, V tiles ----
        const float* kg = k + ((size_t)h * SEQ + (size_t)jb * BSZ) * DIM;
        const float* vg = v + ((size_t)h * SEQ + (size_t)jb * BSZ) * DIM;
        #pragma unroll
        for (int tt = 0; tt < 4; ++tt) {
            int qd  = tid + tt * 256;
            int row = qd >> 4;
            int c4  = (qd & 15) << 2;
            *(float4*)(Ks + row * LDK + c4) = *(const float4*)(kg + row * DIM + c4);
            *(float4*)(Vs + row * LDX + c4) = *(const float4*)(vg + row * DIM + c4);
        }
        __syncthreads();

        // ---- S = Q * K^T : rows r = ty+16rr, cols c = tx+16cc ----
        float s[4][4];
        #pragma unroll
        for (int r = 0; r < 4; ++r)
            #pragma unroll
            for (int c = 0; c < 4; ++c) s[r][c] = 0.f;

        #pragma unroll 4
        for (int d4 = 0; d4 < DIM; d4 += 4) {
            float4 qv[4], kv[4];
            #pragma unroll
            for (int rr = 0; rr < 4; ++rr)
                qv[rr] = *(const float4*)(Qs + (ty + 16 * rr) * LDX + d4);
            #pragma unroll
            for (int cc = 0; cc < 4; ++cc)
                kv[cc] = *(const float4*)(Ks + (tx + 16 * cc) * LDK + d4);
            #pragma unroll
            for (int rr = 0; rr < 4; ++rr)
                #pragma unroll
                for (int cc = 0; cc < 4; ++cc) {
                    s[rr][cc] += qv[rr].x * kv[cc].x + qv[rr].y * kv[cc].y
                               + qv[rr].z * kv[cc].z + qv[rr].w * kv[cc].w;
                }
        }

        // ---- causal mask on diagonal block ----
        if (jb == ib) {
            #pragma unroll
            for (int rr = 0; rr < 4; ++rr) {
                int r = ty + 16 * rr;
                #pragma unroll
                for (int cc = 0; cc < 4; ++cc) {
                    int c = tx + 16 * cc;
                    if (c > r) s[rr][cc] = -1e30f;
                }
            }
        }

        // ---- online softmax (log2 domain) + write P ----
        #pragma unroll
        for (int rr = 0; rr < 4; ++rr) {
            float mloc = fmaxf(fmaxf(s[rr][0], s[rr][1]), fmaxf(s[rr][2], s[rr][3]));
            #pragma unroll
            for (int off = 8; off > 0; off >>= 1)
                mloc = fmaxf(mloc, __shfl_xor_sync(0xffffffffu, mloc, off));
            float mnew  = fmaxf(m_run[rr], mloc);
            float alpha = ex2f_fast(m_run[rr] - mnew);
            float psum  = 0.f;
            const int rbase = (ty + 16 * rr) * LDX + tx;
            #pragma unroll
            for (int cc = 0; cc < 4; ++cc) {
                float p = ex2f_fast(s[rr][cc] - mnew);
                Ps[rbase + 16 * cc] = p;
                psum += p;
            }
            #pragma unroll
            for (int off = 8; off > 0; off >>= 1)
                psum += __shfl_xor_sync(0xffffffffu, psum, off);
            l_run[rr] = l_run[rr] * alpha + psum;
            m_run[rr] = mnew;
            #pragma unroll
            for (int c = 0; c < 4; ++c) acc[rr][c] *= alpha;
        }
        __syncthreads();

        // ---- O += P * V : rows r = ty+16rr, dims d = 4*tx + c ----
        #pragma unroll 4
        for (int c4 = 0; c4 < BSZ; c4 += 4) {
            float4 pv[4], vv[4];
            #pragma unroll
            for (int rr = 0; rr < 4; ++rr)
                pv[rr] = *(const float4*)(Ps + (ty + 16 * rr) * LDX + c4);
            #pragma unroll
            for (int j = 0; j < 4; ++j)
                vv[j] = *(const float4*)(Vs + (c4 + j) * LDX + 4 * tx);
            #pragma unroll
            for (int rr = 0; rr < 4; ++rr) {
                acc[rr][0] += pv[rr].x * vv[0].x + pv[rr].y * vv[1].x
                            + pv[rr].z * vv[2].x + pv[rr].w * vv[3].x;
                acc[rr][1] += pv[rr].x * vv[0].y + pv[rr].y * vv[1].y
                            + pv[rr].z * vv[2].y + pv[rr].w * vv[3].y;
                acc[rr][2] += pv[rr].x * vv[0].z + pv[rr].y * vv[1].z
                            + pv[rr].z * vv[2].z + pv[rr].w * vv[3].z;
                acc[rr][3] += pv[rr].x * vv[0].w + pv[rr].y * vv[1].w
                            + pv[rr].z * vv[2].w + pv[rr].w * vv[3].w;
            }
        }
        __syncthreads();   // protect Ks/Vs/Ps before next iteration's loads
    }

    // ---- epilogue: O / l, coalesced float4 stores ----
    float* og = out + ((size_t)h * SEQ + (size_t)ib * BSZ) * DIM;
    #pragma unroll
    for (int rr = 0; rr < 4; ++rr) {
        float inv = 1.0f / l_run[rr];
        float4 o;
        o.x = acc[rr][0] * inv;
        o.y = acc[rr][1] * inv;
        o.z = acc[rr][2] * inv;
        o.w = acc[rr][3] * inv;
        *(float4*)(og + (ty + 16 * rr) * DIM + 4 * tx) = o;
    }
}

extern "C" void kernel_launch(void* const* d_in, const int* in_sizes, int n_in,
                              void* d_out, int out_size)
{
    const float* q = (const float*)d_in[0];
    const float* k = (const float*)d_in[1];
    const float* v = (const float*)d_in[2];
    float* out = (float*)d_out;

    const int smem_bytes = (BSZ * LDX * 3 + BSZ * LDK) * (int)sizeof(float); // 66560
    cudaFuncSetAttribute(sparse_attn_fp32,
                         cudaFuncAttributeMaxDynamicSharedMemorySize, smem_bytes);

    dim3 grid(NBLK, HEADS);
    sparse_attn_fp32<<<grid, 256, smem_bytes>>>(q, k, v, out);
}

// round 2
// speedup vs baseline: 5.7512x; 5.7512x over previous
#include <cuda_runtime.h>
#include <cuda_fp16.h>
#include <cstdint>

// Sparse block attention: B=1, H=16, S=8192, D=64, BS=64, NB=128
// Pattern per q-block i: {0} U [max(0,i-7), i]; causal inside diagonal block.
// fp16 HMMA (mma.sync.m16n8k16) with register-resident flash softmax.
#define HEADS  16
#define SEQ    8192
#define DIM    64
#define BSZ    64
#define NBLK   128
#define LOCALW 8
#define LDH    72   // half stride: 144B rows -> conflict-free ldmatrix (16B shift/row mod 128B)

__device__ __forceinline__ float ex2f(float x) {
    float y; asm("ex2.approx.ftz.f32 %0, %1;" : "=f"(y) : "f"(x)); return y;
}
__device__ __forceinline__ uint32_t pkh2(float a, float b) {
    __half2 h = __floats2half2_rn(a, b);
    return *reinterpret_cast<uint32_t*>(&h);
}
__device__ __forceinline__ void ldsm_x4(uint32_t& r0, uint32_t& r1, uint32_t& r2, uint32_t& r3, uint32_t a) {
    asm volatile("ldmatrix.sync.aligned.m8n8.x4.shared.b16 {%0,%1,%2,%3}, [%4];"
                 : "=r"(r0), "=r"(r1), "=r"(r2), "=r"(r3) : "r"(a));
}
__device__ __forceinline__ void ldsm_x2(uint32_t& r0, uint32_t& r1, uint32_t a) {
    asm volatile("ldmatrix.sync.aligned.m8n8.x2.shared.b16 {%0,%1}, [%2];"
                 : "=r"(r0), "=r"(r1) : "r"(a));
}
__device__ __forceinline__ void ldsm_x2t(uint32_t& r0, uint32_t& r1, uint32_t a) {
    asm volatile("ldmatrix.sync.aligned.m8n8.x2.trans.shared.b16 {%0,%1}, [%2];"
                 : "=r"(r0), "=r"(r1) : "r"(a));
}
__device__ __forceinline__ void mma16816(float* c, uint32_t a0, uint32_t a1, uint32_t a2, uint32_t a3,
                                         uint32_t b0, uint32_t b1) {
    asm volatile("mma.sync.aligned.m16n8k16.row.col.f32.f16.f16.f32 "
                 "{%0,%1,%2,%3}, {%4,%5,%6,%7}, {%8,%9}, {%0,%1,%2,%3};"
                 : "+f"(c[0]), "+f"(c[1]), "+f"(c[2]), "+f"(c[3])
                 : "r"(a0), "r"(a1), "r"(a2), "r"(a3), "r"(b0), "r"(b1));
}

__global__ __launch_bounds__(128, 4)
void sparse_attn_hmma(const float* __restrict__ q,
                      const float* __restrict__ k,
                      const float* __restrict__ v,
                      float* __restrict__ out)
{
    __shared__ __align__(16) __half Qs[BSZ * LDH];
    __shared__ __align__(16) __half Ks[BSZ * LDH];
    __shared__ __align__(16) __half Vs[BSZ * LDH];

    const int ib   = blockIdx.x;
    const int h    = blockIdx.y;
    const int tid  = threadIdx.x;
    const int lane = tid & 31;
    const int w    = tid >> 5;           // warp 0..3 -> S rows 16w..16w+15

    const float qscale = 0.125f * 1.4426950408889634f;   // sm_scale * log2(e)

    // ---- load + prescale Q tile -> fp16 smem ----
    const float* qg = q + ((size_t)h * SEQ + (size_t)ib * BSZ) * DIM;
    #pragma unroll
    for (int i = tid; i < BSZ * DIM / 4; i += 128) {
        int row = i >> 4;
        int c4  = (i & 15) << 2;
        float4 val = *(const float4*)(qg + row * DIM + c4);
        *(half2*)&Qs[row * LDH + c4]     = __floats2half2_rn(val.x * qscale, val.y * qscale);
        *(half2*)&Qs[row * LDH + c4 + 2] = __floats2half2_rn(val.z * qscale, val.w * qscale);
    }
    __syncthreads();

    const uint32_t qsb = (uint32_t)__cvta_generic_to_shared(Qs);
    const uint32_t ksb = (uint32_t)__cvta_generic_to_shared(Ks);
    const uint32_t vsb = (uint32_t)__cvta_generic_to_shared(Vs);

    // ---- A fragments of Q (persistent across k-blocks): aq[kchunk][0..3] ----
    uint32_t aq[4][4];
    {
        int r   = lane & 15;
        int chi = (lane >> 4) * 8;
        uint32_t base = qsb + (((16 * w + r) * LDH + chi) << 1);
        #pragma unroll
        for (int c = 0; c < 4; ++c)
            ldsm_x4(aq[c][0], aq[c][1], aq[c][2], aq[c][3], base + ((16 * c) << 1));
    }

    // ldmatrix lane address components
    const int l16 = lane & 15;
    const int kr  = l16 & 7;                 // K tile: row within 8
    const int kc8 = ((l16 >> 3) & 1) * 8;    // K tile: k-half select

    float O[8][4];
    #pragma unroll
    for (int j = 0; j < 8; ++j)
        #pragma unroll
        for (int e = 0; e < 4; ++e) O[j][e] = 0.f;
    float m0 = -1e30f, m1 = -1e30f, l0 = 0.f, l1 = 0.f;

    const int r0loc = 16 * w + (lane >> 2);  // local S row of c0/c1
    const int c0loc = 2 * (lane & 3);        // local S col offset within n-tile

    const int nnz = (ib < LOCALW) ? (ib + 1) : (LOCALW + 1);

    for (int t = 0; t < nnz; ++t) {
        const int jb = (ib < LOCALW) ? t : ((t == 0) ? 0 : (ib - LOCALW + t));

        // ---- load K, V tiles -> fp16 smem ----
        const float* kg = k + ((size_t)h * SEQ + (size_t)jb * BSZ) * DIM;
        const float* vg = v + ((size_t)h * SEQ + (size_t)jb * BSZ) * DIM;
        #pragma unroll
        for (int i = tid; i < BSZ * DIM / 4; i += 128) {
            int row = i >> 4;
            int c4  = (i & 15) << 2;
            float4 kv = *(const float4*)(kg + row * DIM + c4);
            *(half2*)&Ks[row * LDH + c4]     = __floats2half2_rn(kv.x, kv.y);
            *(half2*)&Ks[row * LDH + c4 + 2] = __floats2half2_rn(kv.z, kv.w);
            float4 vv = *(const float4*)(vg + row * DIM + c4);
            *(half2*)&Vs[row * LDH + c4]     = __floats2half2_rn(vv.x, vv.y);
            *(half2*)&Vs[row * LDH + c4 + 2] = __floats2half2_rn(vv.z, vv.w);
        }
        __syncthreads();

        // ---- S = Q @ K^T : 8 n-tiles x 4 k-chunks ----
        float S[8][4];
        #pragma unroll
        for (int j = 0; j < 8; ++j)
            #pragma unroll
            for (int e = 0; e < 4; ++e) S[j][e] = 0.f;

        #pragma unroll
        for (int nj = 0; nj < 8; ++nj) {
            uint32_t rowbase = ksb + (((8 * nj + kr) * LDH + kc8) << 1);
            #pragma unroll
            for (int c = 0; c < 4; ++c) {
                uint32_t b0, b1;
                ldsm_x2(b0, b1, rowbase + ((16 * c) << 1));
                mma16816(S[nj], aq[c][0], aq[c][1], aq[c][2], aq[c][3], b0, b1);
            }
        }

        // ---- causal mask on diagonal block ----
        if (jb == ib) {
            #pragma unroll
            for (int nj = 0; nj < 8; ++nj) {
                int cn = 8 * nj + c0loc;
                if (cn     > r0loc)     S[nj][0] = -1e30f;
                if (cn + 1 > r0loc)     S[nj][1] = -1e30f;
                if (cn     > r0loc + 8) S[nj][2] = -1e30f;
                if (cn + 1 > r0loc + 8) S[nj][3] = -1e30f;
            }
        }

        // ---- online softmax (log2 domain), rows r0 (elems 0,1) and r0+8 (elems 2,3) ----
        float mx0 = -1e30f, mx1 = -1e30f;
        #pragma unroll
        for (int nj = 0; nj < 8; ++nj) {
            mx0 = fmaxf(mx0, fmaxf(S[nj][0], S[nj][1]));
            mx1 = fmaxf(mx1, fmaxf(S[nj][2], S[nj][3]));
        }
        mx0 = fmaxf(mx0, __shfl_xor_sync(0xffffffffu, mx0, 1));
        mx0 = fmaxf(mx0, __shfl_xor_sync(0xffffffffu, mx0, 2));
        mx1 = fmaxf(mx1, __shfl_xor_sync(0xffffffffu, mx1, 1));
        mx1 = fmaxf(mx1, __shfl_xor_sync(0xffffffffu, mx1, 2));

        float m0n = fmaxf(m0, mx0), m1n = fmaxf(m1, mx1);
        float a0  = ex2f(m0 - m0n), a1 = ex2f(m1 - m1n);

        float ps0 = 0.f, ps1 = 0.f;
        #pragma unroll
        for (int nj = 0; nj < 8; ++nj) {
            S[nj][0] = ex2f(S[nj][0] - m0n);
            S[nj][1] = ex2f(S[nj][1] - m0n);
            S[nj][2] = ex2f(S[nj][2] - m1n);
            S[nj][3] = ex2f(S[nj][3] - m1n);
            ps0 += S[nj][0] + S[nj][1];
            ps1 += S[nj][2] + S[nj][3];
        }
        ps0 += __shfl_xor_sync(0xffffffffu, ps0, 1);
        ps0 += __shfl_xor_sync(0xffffffffu, ps0, 2);
        ps1 += __shfl_xor_sync(0xffffffffu, ps1, 1);
        ps1 += __shfl_xor_sync(0xffffffffu, ps1, 2);

        l0 = l0 * a0 + ps0;  m0 = m0n;
        l1 = l1 * a1 + ps1;  m1 = m1n;
        #pragma unroll
        for (int nj = 0; nj < 8; ++nj) {
            O[nj][0] *= a0; O[nj][1] *= a0;
            O[nj][2] *= a1; O[nj][3] *= a1;
        }

        // ---- P fragments: direct remap of S accum layout onto A operand ----
        // PV k-chunk c uses S n-tiles 2c (k 0..7) and 2c+1 (k 8..15)
        uint32_t pa[4][4];
        #pragma unroll
        for (int c = 0; c < 4; ++c) {
            pa[c][0] = pkh2(S[2 * c][0],     S[2 * c][1]);      // row r0, k low
            pa[c][1] = pkh2(S[2 * c][2],     S[2 * c][3]);      // row r0+8, k low
            pa[c][2] = pkh2(S[2 * c + 1][0], S[2 * c + 1][1]);  // row r0, k high
            pa[c][3] = pkh2(S[2 * c + 1][2], S[2 * c + 1][3]);  // row r0+8, k high
        }

        // ---- O += P @ V ----
        #pragma unroll
        for (int nj = 0; nj < 8; ++nj) {
            #pragma unroll
            for (int c = 0; c < 4; ++c) {
                uint32_t b0, b1;
                ldsm_x2t(b0, b1, vsb + (((16 * c + l16) * LDH + 8 * nj) << 1));
                mma16816(O[nj], pa[c][0], pa[c][1], pa[c][2], pa[c][3], b0, b1);
            }
        }
        __syncthreads();   // protect Ks/Vs before next iteration's loads
    }

    // ---- epilogue: normalize + store ----
    float inv0 = 1.0f / l0, inv1 = 1.0f / l1;
    float* og = out + ((size_t)h * SEQ + (size_t)ib * BSZ) * DIM;
    #pragma unroll
    for (int nj = 0; nj < 8; ++nj) {
        int cn = 8 * nj + c0loc;
        float2 o0 = make_float2(O[nj][0] * inv0, O[nj][1] * inv0);
        float2 o1 = make_float2(O[nj][2] * inv1, O[nj][3] * inv1);
        *(float2*)(og + r0loc * DIM + cn)       = o0;
        *(float2*)(og + (r0loc + 8) * DIM + cn) = o1;
    }
}

extern "C" void kernel_launch(void* const* d_in, const int* in_sizes, int n_in,
                              void* d_out, int out_size)
{
    const float* q = (const float*)d_in[0];
    const float* k = (const float*)d_in[1];
    const float* v = (const float*)d_in[2];
    float* out = (float*)d_out;

    dim3 grid(NBLK, HEADS);
    sparse_attn_hmma<<<grid, 128>>>(q, k, v, out);
}